// round 1
// baseline (speedup 1.0000x reference)
#include <cuda_runtime.h>

// Problem constants
#define BB 2
#define SS 2048
#define DD 1024
#define HH 16
#define EHD 64
#define MM (BB*SS)   // 4096 rows of activations

// Scratch (device globals — no allocation allowed)
__device__ float g_wq[DD*DD];
__device__ float g_wk[DD*DD];
__device__ float g_wv[DD*DD];
__device__ float g_q[MM*DD];
__device__ float g_k[MM*DD];
__device__ float g_v[MM*DD];
__device__ float g_o[MM*DD];

// ---------------------------------------------------------------------------
// Tiled SGEMM. TB=true:  C[M,N] = A[M,K] @ B[N,K]^T   (both K-major)
//             TB=false: C[M,N] = A[M,K] @ B[K,N]
// 128x128 tile, BK=8, 256 threads, 8x8 per-thread microtile.
// All dims assumed multiples of 128/8 (true here).
// ---------------------------------------------------------------------------
template<bool TB>
__global__ __launch_bounds__(256) void gemm_kernel(const float* __restrict__ A,
                                                   const float* __restrict__ Bm,
                                                   float* __restrict__ C,
                                                   int M, int N, int K)
{
    __shared__ float As[8][128];
    __shared__ float Bs[8][128];
    const int tid = threadIdx.x;
    const int tx = tid & 15;      // 0..15 -> n
    const int ty = tid >> 4;      // 0..15 -> m
    const int m0 = blockIdx.y * 128;
    const int n0 = blockIdx.x * 128;

    float acc[8][8];
#pragma unroll
    for (int i = 0; i < 8; i++)
#pragma unroll
        for (int j = 0; j < 8; j++) acc[i][j] = 0.f;

    for (int k0 = 0; k0 < K; k0 += 8) {
        // load A tile (rows K-major) -> As[k][m]
        {
            const int row = tid >> 1, kq = tid & 1;
            float4 v = *(const float4*)&A[(size_t)(m0 + row) * K + k0 + kq * 4];
            As[kq*4+0][row] = v.x; As[kq*4+1][row] = v.y;
            As[kq*4+2][row] = v.z; As[kq*4+3][row] = v.w;
        }
        if (TB) {
            const int row = tid >> 1, kq = tid & 1;
            float4 v = *(const float4*)&Bm[(size_t)(n0 + row) * K + k0 + kq * 4];
            Bs[kq*4+0][row] = v.x; Bs[kq*4+1][row] = v.y;
            Bs[kq*4+2][row] = v.z; Bs[kq*4+3][row] = v.w;
        } else {
            const int kk = tid >> 5, n4 = tid & 31;
            float4 v = *(const float4*)&Bm[(size_t)(k0 + kk) * N + n0 + n4 * 4];
            *(float4*)&Bs[kk][n4 * 4] = v;
        }
        __syncthreads();

#pragma unroll
        for (int kk = 0; kk < 8; kk++) {
            float a[8], b[8];
            *(float4*)&a[0] = *(const float4*)&As[kk][ty * 8];
            *(float4*)&a[4] = *(const float4*)&As[kk][ty * 8 + 4];
            *(float4*)&b[0] = *(const float4*)&Bs[kk][tx * 8];
            *(float4*)&b[4] = *(const float4*)&Bs[kk][tx * 8 + 4];
#pragma unroll
            for (int i = 0; i < 8; i++)
#pragma unroll
                for (int j = 0; j < 8; j++)
                    acc[i][j] += a[i] * b[j];
        }
        __syncthreads();
    }

#pragma unroll
    for (int i = 0; i < 8; i++) {
        float* crow = &C[(size_t)(m0 + ty * 8 + i) * N + n0 + tx * 8];
        float4 v0, v1;
        v0.x = acc[i][0]; v0.y = acc[i][1]; v0.z = acc[i][2]; v0.w = acc[i][3];
        v1.x = acc[i][4]; v1.y = acc[i][5]; v1.z = acc[i][6]; v1.w = acc[i][7];
        *(float4*)&crow[0] = v0;
        *(float4*)&crow[4] = v1;
    }
}

// ---------------------------------------------------------------------------
// Flash attention, fp32. One thread owns one query row.
// Block: 128 threads = 128 queries. Key tiles of 32.
// grid = (S/128, B*H)
// ---------------------------------------------------------------------------
#define FBM 128
#define FBN 32

__global__ __launch_bounds__(128) void flash_kernel()
{
    __shared__ float Ks[FBN][EHD];   // 8 KB
    __shared__ float Vs[FBN][EHD];   // 8 KB

    const int tid = threadIdx.x;
    const int s0 = blockIdx.x * FBM;
    const int bh = blockIdx.y;
    const int h = bh % HH;
    const int b = bh / HH;
    const int qrow = s0 + tid;

    const float* qptr = &g_q[((size_t)(b * SS + qrow)) * DD + h * EHD];
    float q[EHD];
#pragma unroll
    for (int e4 = 0; e4 < EHD / 4; e4++) {
        float4 v = *(const float4*)&qptr[e4 * 4];
        q[e4*4+0] = v.x; q[e4*4+1] = v.y; q[e4*4+2] = v.z; q[e4*4+3] = v.w;
    }

    float acc[EHD];
#pragma unroll
    for (int e = 0; e < EHD; e++) acc[e] = 0.f;
    float mrow = -1e30f, lrow = 0.f;
    const float scale = 0.125f;   // 1/sqrt(64)

    for (int t0 = 0; t0 < SS; t0 += FBN) {
        __syncthreads();
        // cooperative load of K/V tile: 32x64 floats = 512 float4, 4 per thread
#pragma unroll
        for (int i = 0; i < 4; i++) {
            const int idx = tid + i * 128;       // 0..511
            const int j = idx >> 4, e4 = idx & 15;
            const size_t g = ((size_t)(b * SS + t0 + j)) * DD + h * EHD + e4 * 4;
            *(float4*)&Ks[j][e4 * 4] = *(const float4*)&g_k[g];
            *(float4*)&Vs[j][e4 * 4] = *(const float4*)&g_v[g];
        }
        __syncthreads();

        float s[FBN];
        float tmax = -1e30f;
#pragma unroll
        for (int j = 0; j < FBN; j++) {
            float p0 = 0.f, p1 = 0.f, p2 = 0.f, p3 = 0.f;
#pragma unroll
            for (int e4 = 0; e4 < EHD / 4; e4++) {
                float4 kv = *(const float4*)&Ks[j][e4 * 4];
                p0 += q[e4*4+0] * kv.x;
                p1 += q[e4*4+1] * kv.y;
                p2 += q[e4*4+2] * kv.z;
                p3 += q[e4*4+3] * kv.w;
            }
            float sv = ((p0 + p1) + (p2 + p3)) * scale;
            s[j] = sv;
            tmax = fmaxf(tmax, sv);
        }

        const float mnew = fmaxf(mrow, tmax);
        const float corr = __expf(mrow - mnew);
        lrow *= corr;
#pragma unroll
        for (int e = 0; e < EHD; e++) acc[e] *= corr;

#pragma unroll
        for (int j = 0; j < FBN; j++) {
            const float p = __expf(s[j] - mnew);
            lrow += p;
#pragma unroll
            for (int e4 = 0; e4 < EHD / 4; e4++) {
                float4 vv = *(const float4*)&Vs[j][e4 * 4];
                acc[e4*4+0] += p * vv.x;
                acc[e4*4+1] += p * vv.y;
                acc[e4*4+2] += p * vv.z;
                acc[e4*4+3] += p * vv.w;
            }
        }
        mrow = mnew;
    }

    const float inv = 1.f / lrow;
    float* optr = &g_o[((size_t)(b * SS + qrow)) * DD + h * EHD];
#pragma unroll
    for (int e4 = 0; e4 < EHD / 4; e4++) {
        float4 v;
        v.x = acc[e4*4+0] * inv; v.y = acc[e4*4+1] * inv;
        v.z = acc[e4*4+2] * inv; v.w = acc[e4*4+3] * inv;
        *(float4*)&optr[e4 * 4] = v;
    }
}

// ---------------------------------------------------------------------------
extern "C" void kernel_launch(void* const* d_in, const int* in_sizes, int n_in,
                              void* d_out, int out_size)
{
    (void)in_sizes; (void)n_in; (void)out_size;
    const float* E  = (const float*)d_in[0];
    const float* WQ = (const float*)d_in[1];
    const float* WK = (const float*)d_in[2];
    const float* WV = (const float*)d_in[3];
    const float* WO = (const float*)d_in[4];
    const float* HQ = (const float*)d_in[5];   // [H,64,D] == HQcat [1024,1024]
    const float* HK = (const float*)d_in[6];
    const float* HV = (const float*)d_in[7];
    float* out = (float*)d_out;

    float *wq, *wk, *wv, *q, *k, *v, *o;
    cudaGetSymbolAddress((void**)&wq, g_wq);
    cudaGetSymbolAddress((void**)&wk, g_wk);
    cudaGetSymbolAddress((void**)&wv, g_wv);
    cudaGetSymbolAddress((void**)&q,  g_q);
    cudaGetSymbolAddress((void**)&k,  g_k);
    cudaGetSymbolAddress((void**)&v,  g_v);
    cudaGetSymbolAddress((void**)&o,  g_o);

    dim3 blk(256);
    dim3 gW(DD / 128, DD / 128);     // 8x8   weight prep
    dim3 gA(DD / 128, MM / 128);     // 8x32  activation GEMMs

    // Combined weights: Weff = HXcat @ WX  (NN gemm)
    gemm_kernel<false><<<gW, blk>>>(HQ, WQ, wq, DD, DD, DD);
    gemm_kernel<false><<<gW, blk>>>(HK, WK, wk, DD, DD, DD);
    gemm_kernel<false><<<gW, blk>>>(HV, WV, wv, DD, DD, DD);

    // q/k/v in concatenated-head layout: X = E @ Weff^T  (NT gemm)
    gemm_kernel<true><<<gA, blk>>>(E, wq, q, MM, DD, DD);
    gemm_kernel<true><<<gA, blk>>>(E, wk, k, MM, DD, DD);
    gemm_kernel<true><<<gA, blk>>>(E, wv, v, MM, DD, DD);

    // attention per (b,h), writes concat-head o
    dim3 gF(SS / FBM, BB * HH);
    flash_kernel<<<gF, 128>>>();

    // out = o @ WO^T
    gemm_kernel<true><<<gA, blk>>>(o, WO, out, MM, DD, DD);
}

// round 2
// speedup vs baseline: 2.8915x; 2.8915x over previous
#include <cuda_runtime.h>
#include <cstdint>

#define BB 2
#define SS 2048
#define DD 1024
#define HH 16
#define EHD 64
#define MM (BB*SS)   // 4096

// Scratch (device globals — no allocation allowed)
__device__ float g_wq[DD*DD];
__device__ float g_wk[DD*DD];
__device__ float g_wv[DD*DD];
__device__ float g_q[MM*DD];
__device__ float g_k[MM*DD];
__device__ float g_v[MM*DD];
__device__ float g_o[MM*DD];

__device__ __forceinline__ uint32_t f2tf(float x) {
    uint32_t u; asm("cvt.rna.tf32.f32 %0, %1;" : "=r"(u) : "f"(x)); return u;
}

// D += A * B   (m16n8k8, tf32 in, fp32 accum)
__device__ __forceinline__ void mma8(float* d, const uint32_t* a, const uint32_t* b) {
    asm volatile("mma.sync.aligned.m16n8k8.row.col.f32.tf32.tf32.f32 "
        "{%0,%1,%2,%3}, {%4,%5,%6,%7}, {%8,%9}, {%0,%1,%2,%3};\n"
        : "+f"(d[0]), "+f"(d[1]), "+f"(d[2]), "+f"(d[3])
        : "r"(a[0]), "r"(a[1]), "r"(a[2]), "r"(a[3]), "r"(b[0]), "r"(b[1]));
}

// ---------------------------------------------------------------------------
// TF32 tensor-core GEMM.
//  TB=true : C[M,N] = A[M,K] @ B[N,K]^T
//  TB=false: C[M,N] = A[M,K] @ B[K,N]
// 128x128 tile, BK=16, 256 threads (8 warps, 4x2), warp tile 32x64.
// smem layout As[m][k], Bs[n][k], stride 20 (conflict-free frag loads:
// bank = 20*r + c mod 32 is bijective over the warp).
// ---------------------------------------------------------------------------
template<bool TB>
__global__ __launch_bounds__(256) void gemm_tc(const float* __restrict__ A,
                                               const float* __restrict__ Bm,
                                               float* __restrict__ C,
                                               int M, int N, int K)
{
    __shared__ uint32_t As[128][20];
    __shared__ uint32_t Bs[128][20];
    const int tid  = threadIdx.x;
    const int lane = tid & 31, wid = tid >> 5;
    const int wm = wid & 3, wn = wid >> 2;          // 4 x 2 warp grid
    const int m0 = blockIdx.y * 128, n0 = blockIdx.x * 128;
    const int r = lane >> 2, c = lane & 3;

    float acc[2][8][4] = {};

    for (int k0 = 0; k0 < K; k0 += 16) {
        __syncthreads();
        // A tile: 128 rows x 16 k  (512 float4, 2 per thread)
#pragma unroll
        for (int i = 0; i < 2; i++) {
            int idx = tid + i * 256;
            int row = idx >> 2, kq = idx & 3;
            float4 v = *(const float4*)&A[(size_t)(m0 + row) * K + k0 + kq * 4];
            uint4 u = make_uint4(f2tf(v.x), f2tf(v.y), f2tf(v.z), f2tf(v.w));
            *(uint4*)&As[row][kq * 4] = u;
        }
        if (TB) {
#pragma unroll
            for (int i = 0; i < 2; i++) {
                int idx = tid + i * 256;
                int row = idx >> 2, kq = idx & 3;
                float4 v = *(const float4*)&Bm[(size_t)(n0 + row) * K + k0 + kq * 4];
                uint4 u = make_uint4(f2tf(v.x), f2tf(v.y), f2tf(v.z), f2tf(v.w));
                *(uint4*)&Bs[row][kq * 4] = u;
            }
        } else {
            // B[K,N] rows: lanes spread across k for conflict-free STS
#pragma unroll
            for (int i = 0; i < 2; i++) {
                int idx = tid + i * 256;
                int kk = idx & 15, c4 = idx >> 4;   // c4 in 0..31
                float4 v = *(const float4*)&Bm[(size_t)(k0 + kk) * N + n0 + c4 * 4];
                Bs[c4 * 4 + 0][kk] = f2tf(v.x);
                Bs[c4 * 4 + 1][kk] = f2tf(v.y);
                Bs[c4 * 4 + 2][kk] = f2tf(v.z);
                Bs[c4 * 4 + 3][kk] = f2tf(v.w);
            }
        }
        __syncthreads();

#pragma unroll
        for (int ks = 0; ks < 2; ks++) {
            uint32_t af[2][4], bf2[8][2];
#pragma unroll
            for (int mi = 0; mi < 2; mi++) {
                int mb = wm * 32 + mi * 16;
                af[mi][0] = As[mb + r    ][ks * 8 + c];
                af[mi][1] = As[mb + r + 8][ks * 8 + c];
                af[mi][2] = As[mb + r    ][ks * 8 + c + 4];
                af[mi][3] = As[mb + r + 8][ks * 8 + c + 4];
            }
#pragma unroll
            for (int ni = 0; ni < 8; ni++) {
                int nb = wn * 64 + ni * 8;
                bf2[ni][0] = Bs[nb + r][ks * 8 + c];
                bf2[ni][1] = Bs[nb + r][ks * 8 + c + 4];
            }
#pragma unroll
            for (int mi = 0; mi < 2; mi++)
#pragma unroll
                for (int ni = 0; ni < 8; ni++)
                    mma8(acc[mi][ni], af[mi], bf2[ni]);
        }
    }

#pragma unroll
    for (int mi = 0; mi < 2; mi++)
#pragma unroll
        for (int ni = 0; ni < 8; ni++) {
            int row = m0 + wm * 32 + mi * 16 + r;
            int col = n0 + wn * 64 + ni * 8 + 2 * c;
            *(float2*)&C[(size_t)row * N + col] =
                make_float2(acc[mi][ni][0], acc[mi][ni][1]);
            *(float2*)&C[(size_t)(row + 8) * N + col] =
                make_float2(acc[mi][ni][2], acc[mi][ni][3]);
        }
}

// ---------------------------------------------------------------------------
// Tensor-core flash attention (tf32).
// Block = 128 threads (4 warps) = 64 query rows (16 per warp).
// Key tiles of 32. grid = (S/64, B*H).
// Ks stride 68 / Vs,Ps stride 72 chosen for conflict-free fragment LDS.
// ---------------------------------------------------------------------------
__global__ __launch_bounds__(128) void flash_tc()
{
    __shared__ uint32_t Ks[32][68];
    __shared__ uint32_t Vs[32][72];
    __shared__ uint32_t Ps[4][16][72];

    const int tid  = threadIdx.x;
    const int lane = tid & 31, w = tid >> 5;
    const int r = lane >> 2, c = lane & 3;
    const int s0 = blockIdx.x * 64;
    const int bh = blockIdx.y;
    const int h = bh & (HH - 1), b = bh / HH;

    // Q fragments (pre-scaled by 1/sqrt(64)=0.125, exact under tf32)
    const size_t qbase = (size_t)(b * SS + s0 + w * 16) * DD + h * EHD;
    uint32_t qa[8][4];
#pragma unroll
    for (int kt = 0; kt < 8; kt++) {
        qa[kt][0] = f2tf(0.125f * g_q[qbase + (size_t)r       * DD + kt * 8 + c]);
        qa[kt][1] = f2tf(0.125f * g_q[qbase + (size_t)(r + 8) * DD + kt * 8 + c]);
        qa[kt][2] = f2tf(0.125f * g_q[qbase + (size_t)r       * DD + kt * 8 + c + 4]);
        qa[kt][3] = f2tf(0.125f * g_q[qbase + (size_t)(r + 8) * DD + kt * 8 + c + 4]);
    }

    float o[8][4] = {};
    float m0v = -1e30f, m1v = -1e30f, l0 = 0.f, l1 = 0.f;

    for (int t0 = 0; t0 < SS; t0 += 32) {
        __syncthreads();
        // load K/V tile: 32 rows x 64 cols each, 512 f4 per tile, 4/thread
#pragma unroll
        for (int i = 0; i < 4; i++) {
            int idx = tid + i * 128;
            int trow = idx >> 4, c4 = idx & 15;
            size_t g = (size_t)(b * SS + t0 + trow) * DD + h * EHD + c4 * 4;
            float4 kv = *(const float4*)&g_k[g];
            float4 vv = *(const float4*)&g_v[g];
            *(uint4*)&Ks[trow][c4 * 4] =
                make_uint4(f2tf(kv.x), f2tf(kv.y), f2tf(kv.z), f2tf(kv.w));
            *(uint4*)&Vs[trow][c4 * 4] =
                make_uint4(f2tf(vv.x), f2tf(vv.y), f2tf(vv.z), f2tf(vv.w));
        }
        __syncthreads();

        // S = Q K^T for this warp: 16 x 32 scores (4 n-tiles)
        float sc[4][4] = {};
#pragma unroll
        for (int kst = 0; kst < 8; kst++) {
#pragma unroll
            for (int nt = 0; nt < 4; nt++) {
                uint32_t bf2[2];
                bf2[0] = Ks[nt * 8 + r][kst * 8 + c];
                bf2[1] = Ks[nt * 8 + r][kst * 8 + c + 4];
                mma8(sc[nt], qa[kst], bf2);
            }
        }

        // online softmax (rows r and r+8; 4 lanes per row share via shfl)
        float tmax0 = -1e30f, tmax1 = -1e30f;
#pragma unroll
        for (int nt = 0; nt < 4; nt++) {
            tmax0 = fmaxf(tmax0, fmaxf(sc[nt][0], sc[nt][1]));
            tmax1 = fmaxf(tmax1, fmaxf(sc[nt][2], sc[nt][3]));
        }
        tmax0 = fmaxf(tmax0, __shfl_xor_sync(0xffffffff, tmax0, 1));
        tmax0 = fmaxf(tmax0, __shfl_xor_sync(0xffffffff, tmax0, 2));
        tmax1 = fmaxf(tmax1, __shfl_xor_sync(0xffffffff, tmax1, 1));
        tmax1 = fmaxf(tmax1, __shfl_xor_sync(0xffffffff, tmax1, 2));

        float mn0 = fmaxf(m0v, tmax0), mn1 = fmaxf(m1v, tmax1);
        float cor0 = __expf(m0v - mn0), cor1 = __expf(m1v - mn1);
        m0v = mn0; m1v = mn1;

        float ps0 = 0.f, ps1 = 0.f;
#pragma unroll
        for (int nt = 0; nt < 4; nt++) {
            float p0 = __expf(sc[nt][0] - mn0);
            float p1 = __expf(sc[nt][1] - mn0);
            float p2 = __expf(sc[nt][2] - mn1);
            float p3 = __expf(sc[nt][3] - mn1);
            ps0 += p0 + p1; ps1 += p2 + p3;
            Ps[w][r    ][nt * 8 + 2 * c    ] = f2tf(p0);
            Ps[w][r    ][nt * 8 + 2 * c + 1] = f2tf(p1);
            Ps[w][r + 8][nt * 8 + 2 * c    ] = f2tf(p2);
            Ps[w][r + 8][nt * 8 + 2 * c + 1] = f2tf(p3);
        }
        ps0 += __shfl_xor_sync(0xffffffff, ps0, 1);
        ps0 += __shfl_xor_sync(0xffffffff, ps0, 2);
        ps1 += __shfl_xor_sync(0xffffffff, ps1, 1);
        ps1 += __shfl_xor_sync(0xffffffff, ps1, 2);
        l0 = l0 * cor0 + ps0;
        l1 = l1 * cor1 + ps1;

#pragma unroll
        for (int ne = 0; ne < 8; ne++) {
            o[ne][0] *= cor0; o[ne][1] *= cor0;
            o[ne][2] *= cor1; o[ne][3] *= cor1;
        }

        __syncwarp();

        // O += P V   (k = 32 keys in 4 steps, 8 e-tiles)
#pragma unroll
        for (int k2 = 0; k2 < 4; k2++) {
            uint32_t pa[4];
            pa[0] = Ps[w][r    ][k2 * 8 + c];
            pa[1] = Ps[w][r + 8][k2 * 8 + c];
            pa[2] = Ps[w][r    ][k2 * 8 + c + 4];
            pa[3] = Ps[w][r + 8][k2 * 8 + c + 4];
#pragma unroll
            for (int ne = 0; ne < 8; ne++) {
                uint32_t bf2[2];
                bf2[0] = Vs[k2 * 8 + c    ][ne * 8 + r];
                bf2[1] = Vs[k2 * 8 + c + 4][ne * 8 + r];
                mma8(o[ne], pa, bf2);
            }
        }
    }

    const float inv0 = 1.f / l0, inv1 = 1.f / l1;
    const size_t obase = (size_t)(b * SS + s0 + w * 16) * DD + h * EHD;
#pragma unroll
    for (int ne = 0; ne < 8; ne++) {
        *(float2*)&g_o[obase + (size_t)r       * DD + ne * 8 + 2 * c] =
            make_float2(o[ne][0] * inv0, o[ne][1] * inv0);
        *(float2*)&g_o[obase + (size_t)(r + 8) * DD + ne * 8 + 2 * c] =
            make_float2(o[ne][2] * inv1, o[ne][3] * inv1);
    }
}

// ---------------------------------------------------------------------------
extern "C" void kernel_launch(void* const* d_in, const int* in_sizes, int n_in,
                              void* d_out, int out_size)
{
    (void)in_sizes; (void)n_in; (void)out_size;
    const float* E  = (const float*)d_in[0];
    const float* WQ = (const float*)d_in[1];
    const float* WK = (const float*)d_in[2];
    const float* WV = (const float*)d_in[3];
    const float* WO = (const float*)d_in[4];
    const float* HQ = (const float*)d_in[5];   // [H,64,D] == flat [1024,1024]
    const float* HK = (const float*)d_in[6];
    const float* HV = (const float*)d_in[7];
    float* out = (float*)d_out;

    float *wq, *wk, *wv, *q, *k, *v, *o;
    cudaGetSymbolAddress((void**)&wq, g_wq);
    cudaGetSymbolAddress((void**)&wk, g_wk);
    cudaGetSymbolAddress((void**)&wv, g_wv);
    cudaGetSymbolAddress((void**)&q,  g_q);
    cudaGetSymbolAddress((void**)&k,  g_k);
    cudaGetSymbolAddress((void**)&v,  g_v);
    cudaGetSymbolAddress((void**)&o,  g_o);

    dim3 blk(256);
    dim3 gW(DD / 128, DD / 128);     // weight prep
    dim3 gA(DD / 128, MM / 128);     // activation GEMMs

    // Weff = HXcat @ WX  (NN)
    gemm_tc<false><<<gW, blk>>>(HQ, WQ, wq, DD, DD, DD);
    gemm_tc<false><<<gW, blk>>>(HK, WK, wk, DD, DD, DD);
    gemm_tc<false><<<gW, blk>>>(HV, WV, wv, DD, DD, DD);

    // q/k/v (concat-head layout): X = E @ Weff^T  (NT)
    gemm_tc<true><<<gA, blk>>>(E, wq, q, MM, DD, DD);
    gemm_tc<true><<<gA, blk>>>(E, wk, k, MM, DD, DD);
    gemm_tc<true><<<gA, blk>>>(E, wv, v, MM, DD, DD);

    // attention per (b,h)
    dim3 gF(SS / 64, BB * HH);
    flash_tc<<<gF, 128>>>();

    // out = o @ WO^T
    gemm_tc<true><<<gA, blk>>>(o, WO, out, MM, DD, DD);
}

// round 3
// speedup vs baseline: 3.7245x; 1.2881x over previous
#include <cuda_runtime.h>
#include <cstdint>

#define BB 2
#define SS 2048
#define DD 1024
#define HH 16
#define EHD 64
#define MM (BB*SS)   // 4096

__device__ float g_wq[DD*DD];
__device__ float g_wk[DD*DD];
__device__ float g_wv[DD*DD];
__device__ float g_q[MM*DD];
__device__ float g_k[MM*DD];
__device__ float g_v[MM*DD];
__device__ float g_o[MM*DD];

__device__ __forceinline__ uint32_t f2tf(float x) {
    uint32_t u; asm("cvt.rna.tf32.f32 %0, %1;" : "=r"(u) : "f"(x)); return u;
}

__device__ __forceinline__ void mma8(float* d, const uint32_t* a, const uint32_t* b) {
    asm volatile("mma.sync.aligned.m16n8k8.row.col.f32.tf32.tf32.f32 "
        "{%0,%1,%2,%3}, {%4,%5,%6,%7}, {%8,%9}, {%0,%1,%2,%3};\n"
        : "+f"(d[0]), "+f"(d[1]), "+f"(d[2]), "+f"(d[3])
        : "r"(a[0]), "r"(a[1]), "r"(a[2]), "r"(a[3]), "r"(b[0]), "r"(b[1]));
}

struct GemmBatch {
    const float* A[3];
    const float* B[3];
    float*       C[3];
};

// ---------------------------------------------------------------------------
// TF32 tensor-core GEMM, z-batched, software-pipelined (reg prefetch).
//  TB=true : C = A[M,K] @ B[N,K]^T ;  TB=false: C = A[M,K] @ B[K,N]
// 128x128 tile, BK=16, 256 threads (8 warps, 4x2), warp tile 32x64.
// ---------------------------------------------------------------------------
template<bool TB>
__global__ __launch_bounds__(256) void gemm_tc(GemmBatch gb, int M, int N, int K)
{
    __shared__ uint32_t As[128][20];
    __shared__ uint32_t Bs[128][20];
    const float* __restrict__ A  = gb.A[blockIdx.z];
    const float* __restrict__ Bm = gb.B[blockIdx.z];
    float* __restrict__ C        = gb.C[blockIdx.z];

    const int tid  = threadIdx.x;
    const int lane = tid & 31, wid = tid >> 5;
    const int wm = wid & 3, wn = wid >> 2;
    const int m0 = blockIdx.y * 128, n0 = blockIdx.x * 128;
    const int r = lane >> 2, c = lane & 3;

    float acc[2][8][4] = {};

    // prefetch indices
    const int arow = tid >> 2, akq = tid & 3;          // A/B(TB) tile coords
    const int bkk  = tid & 15, bc4 = tid >> 4;         // B(NN) tile coords

    float4 pa[2], pb[2];
    // prologue loads (k0 = 0)
#pragma unroll
    for (int i = 0; i < 2; i++) {
        int idx = tid + i * 256;
        int row = idx >> 2, kq = idx & 3;
        pa[i] = *(const float4*)&A[(size_t)(m0 + row) * K + kq * 4];
    }
    if (TB) {
#pragma unroll
        for (int i = 0; i < 2; i++) {
            int idx = tid + i * 256;
            int row = idx >> 2, kq = idx & 3;
            pb[i] = *(const float4*)&Bm[(size_t)(n0 + row) * K + kq * 4];
        }
    } else {
#pragma unroll
        for (int i = 0; i < 2; i++) {
            int idx = tid + i * 256;
            int kk = idx & 15, c4 = idx >> 4;
            pb[i] = *(const float4*)&Bm[(size_t)kk * N + n0 + c4 * 4];
        }
    }

    for (int k0 = 0; k0 < K; k0 += 16) {
        // store current prefetch to smem
#pragma unroll
        for (int i = 0; i < 2; i++) {
            int idx = tid + i * 256;
            int row = idx >> 2, kq = idx & 3;
            *(uint4*)&As[row][kq * 4] =
                make_uint4(f2tf(pa[i].x), f2tf(pa[i].y), f2tf(pa[i].z), f2tf(pa[i].w));
        }
        if (TB) {
#pragma unroll
            for (int i = 0; i < 2; i++) {
                int idx = tid + i * 256;
                int row = idx >> 2, kq = idx & 3;
                *(uint4*)&Bs[row][kq * 4] =
                    make_uint4(f2tf(pb[i].x), f2tf(pb[i].y), f2tf(pb[i].z), f2tf(pb[i].w));
            }
        } else {
#pragma unroll
            for (int i = 0; i < 2; i++) {
                int idx = tid + i * 256;
                int kk = idx & 15, c4 = idx >> 4;
                Bs[c4 * 4 + 0][kk] = f2tf(pb[i].x);
                Bs[c4 * 4 + 1][kk] = f2tf(pb[i].y);
                Bs[c4 * 4 + 2][kk] = f2tf(pb[i].z);
                Bs[c4 * 4 + 3][kk] = f2tf(pb[i].w);
            }
        }
        __syncthreads();

        // prefetch next tile (overlaps with compute below)
        const int kn = k0 + 16;
        if (kn < K) {
#pragma unroll
            for (int i = 0; i < 2; i++) {
                int idx = tid + i * 256;
                int row = idx >> 2, kq = idx & 3;
                pa[i] = *(const float4*)&A[(size_t)(m0 + row) * K + kn + kq * 4];
            }
            if (TB) {
#pragma unroll
                for (int i = 0; i < 2; i++) {
                    int idx = tid + i * 256;
                    int row = idx >> 2, kq = idx & 3;
                    pb[i] = *(const float4*)&Bm[(size_t)(n0 + row) * K + kn + kq * 4];
                }
            } else {
#pragma unroll
                for (int i = 0; i < 2; i++) {
                    int idx = tid + i * 256;
                    int kk = idx & 15, c4 = idx >> 4;
                    pb[i] = *(const float4*)&Bm[(size_t)(kn + kk) * N + n0 + c4 * 4];
                }
            }
        }

#pragma unroll
        for (int ks = 0; ks < 2; ks++) {
            uint32_t af[2][4], bf2[8][2];
#pragma unroll
            for (int mi = 0; mi < 2; mi++) {
                int mb = wm * 32 + mi * 16;
                af[mi][0] = As[mb + r    ][ks * 8 + c];
                af[mi][1] = As[mb + r + 8][ks * 8 + c];
                af[mi][2] = As[mb + r    ][ks * 8 + c + 4];
                af[mi][3] = As[mb + r + 8][ks * 8 + c + 4];
            }
#pragma unroll
            for (int ni = 0; ni < 8; ni++) {
                int nb = wn * 64 + ni * 8;
                bf2[ni][0] = Bs[nb + r][ks * 8 + c];
                bf2[ni][1] = Bs[nb + r][ks * 8 + c + 4];
            }
#pragma unroll
            for (int mi = 0; mi < 2; mi++)
#pragma unroll
                for (int ni = 0; ni < 8; ni++)
                    mma8(acc[mi][ni], af[mi], bf2[ni]);
        }
        __syncthreads();
    }

#pragma unroll
    for (int mi = 0; mi < 2; mi++)
#pragma unroll
        for (int ni = 0; ni < 8; ni++) {
            int row = m0 + wm * 32 + mi * 16 + r;
            int col = n0 + wn * 64 + ni * 8 + 2 * c;
            *(float2*)&C[(size_t)row * N + col] =
                make_float2(acc[mi][ni][0], acc[mi][ni][1]);
            *(float2*)&C[(size_t)(row + 8) * N + col] =
                make_float2(acc[mi][ni][2], acc[mi][ni][3]);
        }
}

// ---------------------------------------------------------------------------
// Tensor-core flash attention (tf32), 4 warps, 32 q-rows per warp (2 m-tiles),
// key tiles of 32. grid = (S/128, B*H).
// ---------------------------------------------------------------------------
__global__ __launch_bounds__(128, 2) void flash_tc()
{
    __shared__ uint32_t Ks[32][68];        // [key][e]  stride%32==4 -> conflict-free frags
    __shared__ uint32_t Vs[32][72];        // [key][e]  stride%32==8 -> conflict-free frags
    __shared__ uint32_t Ps[4][32][36];     // per-warp P, stride%32==4

    const int tid  = threadIdx.x;
    const int lane = tid & 31, w = tid >> 5;
    const int r = lane >> 2, c = lane & 3;
    const int s0 = blockIdx.x * 128;
    const int bh = blockIdx.y;
    const int h = bh & (HH - 1), b = bh / HH;

    // Q fragments, pre-scaled by 0.125 (exact)
    uint32_t qa[2][8][4];
#pragma unroll
    for (int mi = 0; mi < 2; mi++) {
        const size_t qb = (size_t)(b * SS + s0 + w * 32 + mi * 16) * DD + h * EHD;
#pragma unroll
        for (int kt = 0; kt < 8; kt++) {
            qa[mi][kt][0] = f2tf(0.125f * g_q[qb + (size_t)r       * DD + kt * 8 + c]);
            qa[mi][kt][1] = f2tf(0.125f * g_q[qb + (size_t)(r + 8) * DD + kt * 8 + c]);
            qa[mi][kt][2] = f2tf(0.125f * g_q[qb + (size_t)r       * DD + kt * 8 + c + 4]);
            qa[mi][kt][3] = f2tf(0.125f * g_q[qb + (size_t)(r + 8) * DD + kt * 8 + c + 4]);
        }
    }

    float o[2][8][4] = {};
    float mv[2][2], lv[2][2];
#pragma unroll
    for (int mi = 0; mi < 2; mi++) { mv[mi][0] = mv[mi][1] = -1e30f; lv[mi][0] = lv[mi][1] = 0.f; }

    for (int t0 = 0; t0 < SS; t0 += 32) {
        __syncthreads();
#pragma unroll
        for (int i = 0; i < 4; i++) {
            int idx = tid + i * 128;
            int trow = idx >> 4, c4 = idx & 15;
            size_t g = (size_t)(b * SS + t0 + trow) * DD + h * EHD + c4 * 4;
            float4 kv = *(const float4*)&g_k[g];
            float4 vv = *(const float4*)&g_v[g];
            *(uint4*)&Ks[trow][c4 * 4] =
                make_uint4(f2tf(kv.x), f2tf(kv.y), f2tf(kv.z), f2tf(kv.w));
            *(uint4*)&Vs[trow][c4 * 4] =
                make_uint4(f2tf(vv.x), f2tf(vv.y), f2tf(vv.z), f2tf(vv.w));
        }
        __syncthreads();

        // S = Q K^T : per warp 32x32 (2 m-tiles x 4 n-tiles), B-frag reused x2
        float sc[2][4][4] = {};
#pragma unroll
        for (int kst = 0; kst < 8; kst++) {
#pragma unroll
            for (int nt = 0; nt < 4; nt++) {
                uint32_t bf2[2];
                bf2[0] = Ks[nt * 8 + r][kst * 8 + c];
                bf2[1] = Ks[nt * 8 + r][kst * 8 + c + 4];
                mma8(sc[0][nt], qa[0][kst], bf2);
                mma8(sc[1][nt], qa[1][kst], bf2);
            }
        }

        // online softmax per m-tile
        bool need_rescale = false;
        float cor[2][2];
#pragma unroll
        for (int mi = 0; mi < 2; mi++) {
            float t0m = -1e30f, t1m = -1e30f;
#pragma unroll
            for (int nt = 0; nt < 4; nt++) {
                t0m = fmaxf(t0m, fmaxf(sc[mi][nt][0], sc[mi][nt][1]));
                t1m = fmaxf(t1m, fmaxf(sc[mi][nt][2], sc[mi][nt][3]));
            }
            t0m = fmaxf(t0m, __shfl_xor_sync(0xffffffff, t0m, 1));
            t0m = fmaxf(t0m, __shfl_xor_sync(0xffffffff, t0m, 2));
            t1m = fmaxf(t1m, __shfl_xor_sync(0xffffffff, t1m, 1));
            t1m = fmaxf(t1m, __shfl_xor_sync(0xffffffff, t1m, 2));

            float mn0 = fmaxf(mv[mi][0], t0m), mn1 = fmaxf(mv[mi][1], t1m);
            cor[mi][0] = __expf(mv[mi][0] - mn0);
            cor[mi][1] = __expf(mv[mi][1] - mn1);
            need_rescale |= (mn0 > mv[mi][0]) || (mn1 > mv[mi][1]);
            mv[mi][0] = mn0; mv[mi][1] = mn1;

            float ps0 = 0.f, ps1 = 0.f;
#pragma unroll
            for (int nt = 0; nt < 4; nt++) {
                float p0 = __expf(sc[mi][nt][0] - mn0);
                float p1 = __expf(sc[mi][nt][1] - mn0);
                float p2 = __expf(sc[mi][nt][2] - mn1);
                float p3 = __expf(sc[mi][nt][3] - mn1);
                ps0 += p0 + p1; ps1 += p2 + p3;
                Ps[w][mi * 16 + r    ][nt * 8 + 2 * c    ] = f2tf(p0);
                Ps[w][mi * 16 + r    ][nt * 8 + 2 * c + 1] = f2tf(p1);
                Ps[w][mi * 16 + r + 8][nt * 8 + 2 * c    ] = f2tf(p2);
                Ps[w][mi * 16 + r + 8][nt * 8 + 2 * c + 1] = f2tf(p3);
            }
            ps0 += __shfl_xor_sync(0xffffffff, ps0, 1);
            ps0 += __shfl_xor_sync(0xffffffff, ps0, 2);
            ps1 += __shfl_xor_sync(0xffffffff, ps1, 1);
            ps1 += __shfl_xor_sync(0xffffffff, ps1, 2);
            lv[mi][0] = lv[mi][0] * cor[mi][0] + ps0;
            lv[mi][1] = lv[mi][1] * cor[mi][1] + ps1;
        }

        // deferred O rescale: skip entirely if no row max advanced (warp-uniform)
        if (__ballot_sync(0xffffffff, need_rescale)) {
#pragma unroll
            for (int mi = 0; mi < 2; mi++)
#pragma unroll
                for (int ne = 0; ne < 8; ne++) {
                    o[mi][ne][0] *= cor[mi][0]; o[mi][ne][1] *= cor[mi][0];
                    o[mi][ne][2] *= cor[mi][1]; o[mi][ne][3] *= cor[mi][1];
                }
        }

        __syncwarp();

        // O += P V (k = 32 keys in 4 steps, 8 e-tiles, B-frag reused x2)
#pragma unroll
        for (int k2 = 0; k2 < 4; k2++) {
            uint32_t pa0[4], pa1[4];
            pa0[0] = Ps[w][r    ][k2 * 8 + c];
            pa0[1] = Ps[w][r + 8][k2 * 8 + c];
            pa0[2] = Ps[w][r    ][k2 * 8 + c + 4];
            pa0[3] = Ps[w][r + 8][k2 * 8 + c + 4];
            pa1[0] = Ps[w][16 + r    ][k2 * 8 + c];
            pa1[1] = Ps[w][16 + r + 8][k2 * 8 + c];
            pa1[2] = Ps[w][16 + r    ][k2 * 8 + c + 4];
            pa1[3] = Ps[w][16 + r + 8][k2 * 8 + c + 4];
#pragma unroll
            for (int ne = 0; ne < 8; ne++) {
                uint32_t bf2[2];
                bf2[0] = Vs[k2 * 8 + c    ][ne * 8 + r];
                bf2[1] = Vs[k2 * 8 + c + 4][ne * 8 + r];
                mma8(o[0][ne], pa0, bf2);
                mma8(o[1][ne], pa1, bf2);
            }
        }
    }

#pragma unroll
    for (int mi = 0; mi < 2; mi++) {
        const float inv0 = 1.f / lv[mi][0], inv1 = 1.f / lv[mi][1];
        const size_t ob = (size_t)(b * SS + s0 + w * 32 + mi * 16) * DD + h * EHD;
#pragma unroll
        for (int ne = 0; ne < 8; ne++) {
            *(float2*)&g_o[ob + (size_t)r       * DD + ne * 8 + 2 * c] =
                make_float2(o[mi][ne][0] * inv0, o[mi][ne][1] * inv0);
            *(float2*)&g_o[ob + (size_t)(r + 8) * DD + ne * 8 + 2 * c] =
                make_float2(o[mi][ne][2] * inv1, o[mi][ne][3] * inv1);
        }
    }
}

// ---------------------------------------------------------------------------
extern "C" void kernel_launch(void* const* d_in, const int* in_sizes, int n_in,
                              void* d_out, int out_size)
{
    (void)in_sizes; (void)n_in; (void)out_size;
    const float* E  = (const float*)d_in[0];
    const float* WQ = (const float*)d_in[1];
    const float* WK = (const float*)d_in[2];
    const float* WV = (const float*)d_in[3];
    const float* WO = (const float*)d_in[4];
    const float* HQ = (const float*)d_in[5];
    const float* HK = (const float*)d_in[6];
    const float* HV = (const float*)d_in[7];
    float* out = (float*)d_out;

    float *wq, *wk, *wv, *q, *k, *v, *o;
    cudaGetSymbolAddress((void**)&wq, g_wq);
    cudaGetSymbolAddress((void**)&wk, g_wk);
    cudaGetSymbolAddress((void**)&wv, g_wv);
    cudaGetSymbolAddress((void**)&q,  g_q);
    cudaGetSymbolAddress((void**)&k,  g_k);
    cudaGetSymbolAddress((void**)&v,  g_v);
    cudaGetSymbolAddress((void**)&o,  g_o);

    dim3 blk(256);

    // 1) Weff = HXcat @ WX (NN), batched z=3
    GemmBatch gw;
    gw.A[0] = HQ; gw.B[0] = WQ; gw.C[0] = wq;
    gw.A[1] = HK; gw.B[1] = WK; gw.C[1] = wk;
    gw.A[2] = HV; gw.B[2] = WV; gw.C[2] = wv;
    gemm_tc<false><<<dim3(DD/128, DD/128, 3), blk>>>(gw, DD, DD, DD);

    // 2) q/k/v = E @ Weff^T (NT), batched z=3
    GemmBatch ga;
    ga.A[0] = E; ga.B[0] = wq; ga.C[0] = q;
    ga.A[1] = E; ga.B[1] = wk; ga.C[1] = k;
    ga.A[2] = E; ga.B[2] = wv; ga.C[2] = v;
    gemm_tc<true><<<dim3(DD/128, MM/128, 3), blk>>>(ga, MM, DD, DD);

    // 3) attention
    flash_tc<<<dim3(SS/128, BB*HH), 128>>>();

    // 4) out = o @ WO^T
    GemmBatch go;
    go.A[0] = o; go.B[0] = WO; go.C[0] = out;
    go.A[1] = o; go.B[1] = WO; go.C[1] = out;   // unused
    go.A[2] = o; go.B[2] = WO; go.C[2] = out;   // unused
    gemm_tc<true><<<dim3(DD/128, MM/128, 1), blk>>>(go, MM, DD, DD);
}

// round 5
// speedup vs baseline: 4.0563x; 1.0891x over previous
#include <cuda_runtime.h>
#include <cstdint>

#define BB 2
#define SS 2048
#define DD 1024
#define HH 16
#define EHD 64
#define MM (BB*SS)   // 4096

__device__ float g_wq[DD*DD];
__device__ float g_wk[DD*DD];
__device__ float g_wv[DD*DD];
__device__ float g_q[MM*DD];
__device__ float g_k[MM*DD];
__device__ float g_v[MM*DD];
__device__ float g_o[MM*DD];

__device__ __forceinline__ uint32_t f2tf(float x) {
    uint32_t u; asm("cvt.rna.tf32.f32 %0, %1;" : "=r"(u) : "f"(x)); return u;
}

__device__ __forceinline__ uint32_t smem_u32(const void* p) {
    uint32_t a;
    asm("{ .reg .u64 t; cvta.to.shared.u64 t, %1; cvt.u32.u64 %0, t; }"
        : "=r"(a) : "l"(p));
    return a;
}

__device__ __forceinline__ void ldsm4(uint32_t* d, uint32_t addr) {
    asm volatile("ldmatrix.sync.aligned.m8n8.x4.shared.b16 {%0,%1,%2,%3}, [%4];"
        : "=r"(d[0]), "=r"(d[1]), "=r"(d[2]), "=r"(d[3]) : "r"(addr));
}

__device__ __forceinline__ void mma8(float* d, const uint32_t* a, const uint32_t* b) {
    asm volatile("mma.sync.aligned.m16n8k8.row.col.f32.tf32.tf32.f32 "
        "{%0,%1,%2,%3}, {%4,%5,%6,%7}, {%8,%9}, {%0,%1,%2,%3};\n"
        : "+f"(d[0]), "+f"(d[1]), "+f"(d[2]), "+f"(d[3])
        : "r"(a[0]), "r"(a[1]), "r"(a[2]), "r"(a[3]), "r"(b[0]), "r"(b[1]));
}

struct GemmBatch {
    const float* A[3];
    const float* B[3];
    float*       C[3];
};

// ---------------------------------------------------------------------------
// TF32 tensor-core GEMM, z-batched, reg-prefetch pipeline, LDSM fragments.
//  TB=true : C = A[M,K] @ B[N,K]^T ;  TB=false: C = A[M,K] @ B[K,N]
// 128x128 tile, BK=16, 256 threads (8 warps, 4x2), warp tile 32x64.
// smem stride 20 words: conflict-free for both STS and LDSM phases.
// ---------------------------------------------------------------------------
template<bool TB>
__global__ __launch_bounds__(256) void gemm_tc(GemmBatch gb, int M, int N, int K)
{
    __shared__ uint32_t As[128][20];
    __shared__ uint32_t Bs[128][20];
    const float* __restrict__ A  = gb.A[blockIdx.z];
    const float* __restrict__ Bm = gb.B[blockIdx.z];
    float* __restrict__ C        = gb.C[blockIdx.z];

    const int tid  = threadIdx.x;
    const int lane = tid & 31, wid = tid >> 5;
    const int wm = wid & 3, wn = wid >> 2;
    const int m0 = blockIdx.y * 128, n0 = blockIdx.x * 128;
    const int r = lane >> 2, c = lane & 3;

    // LDSM per-lane address components
    const int l15   = lane & 15;
    const int khalf = (lane >> 4) & 1;            // A/P: k half
    const int b_r   = (lane & 7) + ((lane & 16) >> 1);
    const int b_k4  = (lane & 8) >> 1;

    const uint32_t As_base = smem_u32(&As[0][0]);
    const uint32_t Bs_base = smem_u32(&Bs[0][0]);
    const uint32_t a_addr0 = As_base + (((wm * 32 + l15) * 20 + 4 * khalf) << 2);
    const uint32_t b_addr0 = Bs_base + (((wn * 64 + b_r) * 20 + b_k4) << 2);

    float acc[2][8][4] = {};

    float4 pa[2], pb[2];
#pragma unroll
    for (int i = 0; i < 2; i++) {
        int idx = tid + i * 256;
        int row = idx >> 2, kq = idx & 3;
        pa[i] = *(const float4*)&A[(size_t)(m0 + row) * K + kq * 4];
    }
    if (TB) {
#pragma unroll
        for (int i = 0; i < 2; i++) {
            int idx = tid + i * 256;
            int row = idx >> 2, kq = idx & 3;
            pb[i] = *(const float4*)&Bm[(size_t)(n0 + row) * K + kq * 4];
        }
    } else {
#pragma unroll
        for (int i = 0; i < 2; i++) {
            int idx = tid + i * 256;
            int kk = idx & 15, c4 = idx >> 4;
            pb[i] = *(const float4*)&Bm[(size_t)kk * N + n0 + c4 * 4];
        }
    }

    for (int k0 = 0; k0 < K; k0 += 16) {
#pragma unroll
        for (int i = 0; i < 2; i++) {
            int idx = tid + i * 256;
            int row = idx >> 2, kq = idx & 3;
            *(uint4*)&As[row][kq * 4] =
                make_uint4(f2tf(pa[i].x), f2tf(pa[i].y), f2tf(pa[i].z), f2tf(pa[i].w));
        }
        if (TB) {
#pragma unroll
            for (int i = 0; i < 2; i++) {
                int idx = tid + i * 256;
                int row = idx >> 2, kq = idx & 3;
                *(uint4*)&Bs[row][kq * 4] =
                    make_uint4(f2tf(pb[i].x), f2tf(pb[i].y), f2tf(pb[i].z), f2tf(pb[i].w));
            }
        } else {
#pragma unroll
            for (int i = 0; i < 2; i++) {
                int idx = tid + i * 256;
                int kk = idx & 15, c4 = idx >> 4;
                Bs[c4 * 4 + 0][kk] = f2tf(pb[i].x);
                Bs[c4 * 4 + 1][kk] = f2tf(pb[i].y);
                Bs[c4 * 4 + 2][kk] = f2tf(pb[i].z);
                Bs[c4 * 4 + 3][kk] = f2tf(pb[i].w);
            }
        }
        __syncthreads();

        const int kn = k0 + 16;
        if (kn < K) {
#pragma unroll
            for (int i = 0; i < 2; i++) {
                int idx = tid + i * 256;
                int row = idx >> 2, kq = idx & 3;
                pa[i] = *(const float4*)&A[(size_t)(m0 + row) * K + kn + kq * 4];
            }
            if (TB) {
#pragma unroll
                for (int i = 0; i < 2; i++) {
                    int idx = tid + i * 256;
                    int row = idx >> 2, kq = idx & 3;
                    pb[i] = *(const float4*)&Bm[(size_t)(n0 + row) * K + kn + kq * 4];
                }
            } else {
#pragma unroll
                for (int i = 0; i < 2; i++) {
                    int idx = tid + i * 256;
                    int kk = idx & 15, c4 = idx >> 4;
                    pb[i] = *(const float4*)&Bm[(size_t)(kn + kk) * N + n0 + c4 * 4];
                }
            }
        }

#pragma unroll
        for (int ks = 0; ks < 2; ks++) {
            uint32_t af[2][4], bf[4][4];
            ldsm4(af[0], a_addr0 + ((ks * 8) << 2));
            ldsm4(af[1], a_addr0 + ((16 * 20 + ks * 8) << 2));
#pragma unroll
            for (int nj = 0; nj < 4; nj++)
                ldsm4(bf[nj], b_addr0 + ((nj * 16 * 20 + ks * 8) << 2));
#pragma unroll
            for (int mi = 0; mi < 2; mi++)
#pragma unroll
                for (int ni = 0; ni < 8; ni++)
                    mma8(acc[mi][ni], af[mi], &bf[ni >> 1][(ni & 1) * 2]);
        }
        __syncthreads();
    }

#pragma unroll
    for (int mi = 0; mi < 2; mi++)
#pragma unroll
        for (int ni = 0; ni < 8; ni++) {
            int row = m0 + wm * 32 + mi * 16 + r;
            int col = n0 + wn * 64 + ni * 8 + 2 * c;
            *(float2*)&C[(size_t)row * N + col] =
                make_float2(acc[mi][ni][0], acc[mi][ni][1]);
            *(float2*)&C[(size_t)(row + 8) * N + col] =
                make_float2(acc[mi][ni][2], acc[mi][ni][3]);
        }
}

// ---------------------------------------------------------------------------
// Tensor-core flash attention (tf32), 4 warps, 32 q-rows/warp, key tiles 32.
// LDSM for K-fragments (S-phase) and P-fragments (PV-phase).
// grid = (S/128, B*H).
// ---------------------------------------------------------------------------
__global__ __launch_bounds__(128, 2) void flash_tc()
{
    __shared__ uint32_t Ks[32][68];
    __shared__ uint32_t Vs[32][72];
    __shared__ uint32_t Ps[4][32][36];

    const int tid  = threadIdx.x;
    const int lane = tid & 31, w = tid >> 5;
    const int r = lane >> 2, c = lane & 3;
    const int s0 = blockIdx.x * 128;
    const int bh = blockIdx.y;
    const int h = bh & (HH - 1), b = bh / HH;

    const int l15   = lane & 15;
    const int khalf = (lane >> 4) & 1;
    const int b_r   = (lane & 7) + ((lane & 16) >> 1);
    const int b_k4  = (lane & 8) >> 1;

    const uint32_t ks_addr = smem_u32(&Ks[0][0]) + ((b_r * 68 + b_k4) << 2);
    const uint32_t ps_addr = smem_u32(&Ps[w][0][0]) + ((l15 * 36 + 4 * khalf) << 2);

    uint32_t qa[2][8][4];
#pragma unroll
    for (int mi = 0; mi < 2; mi++) {
        const size_t qb = (size_t)(b * SS + s0 + w * 32 + mi * 16) * DD + h * EHD;
#pragma unroll
        for (int kt = 0; kt < 8; kt++) {
            qa[mi][kt][0] = f2tf(0.125f * g_q[qb + (size_t)r       * DD + kt * 8 + c]);
            qa[mi][kt][1] = f2tf(0.125f * g_q[qb + (size_t)(r + 8) * DD + kt * 8 + c]);
            qa[mi][kt][2] = f2tf(0.125f * g_q[qb + (size_t)r       * DD + kt * 8 + c + 4]);
            qa[mi][kt][3] = f2tf(0.125f * g_q[qb + (size_t)(r + 8) * DD + kt * 8 + c + 4]);
        }
    }

    float o[2][8][4] = {};
    float mv[2][2], lv[2][2];
#pragma unroll
    for (int mi = 0; mi < 2; mi++) { mv[mi][0] = mv[mi][1] = -1e30f; lv[mi][0] = lv[mi][1] = 0.f; }

    for (int t0 = 0; t0 < SS; t0 += 32) {
        __syncthreads();
#pragma unroll
        for (int i = 0; i < 4; i++) {
            int idx = tid + i * 128;
            int trow = idx >> 4, c4 = idx & 15;
            size_t g = (size_t)(b * SS + t0 + trow) * DD + h * EHD + c4 * 4;
            float4 kv = *(const float4*)&g_k[g];
            float4 vv = *(const float4*)&g_v[g];
            *(uint4*)&Ks[trow][c4 * 4] =
                make_uint4(f2tf(kv.x), f2tf(kv.y), f2tf(kv.z), f2tf(kv.w));
            *(uint4*)&Vs[trow][c4 * 4] =
                make_uint4(f2tf(vv.x), f2tf(vv.y), f2tf(vv.z), f2tf(vv.w));
        }
        __syncthreads();

        // S = Q K^T : 32x32 per warp; K B-frags via LDSM (2 x4 per kst)
        float sc[2][4][4] = {};
#pragma unroll
        for (int kst = 0; kst < 8; kst++) {
            uint32_t kb[2][4];
            ldsm4(kb[0], ks_addr + ((kst * 8) << 2));
            ldsm4(kb[1], ks_addr + ((16 * 68 + kst * 8) << 2));
#pragma unroll
            for (int nt = 0; nt < 4; nt++) {
                mma8(sc[0][nt], qa[0][kst], &kb[nt >> 1][(nt & 1) * 2]);
                mma8(sc[1][nt], qa[1][kst], &kb[nt >> 1][(nt & 1) * 2]);
            }
        }

        // online softmax per m-tile
        bool need_rescale = false;
        float cor[2][2];
#pragma unroll
        for (int mi = 0; mi < 2; mi++) {
            float t0m = -1e30f, t1m = -1e30f;
#pragma unroll
            for (int nt = 0; nt < 4; nt++) {
                t0m = fmaxf(t0m, fmaxf(sc[mi][nt][0], sc[mi][nt][1]));
                t1m = fmaxf(t1m, fmaxf(sc[mi][nt][2], sc[mi][nt][3]));
            }
            t0m = fmaxf(t0m, __shfl_xor_sync(0xffffffff, t0m, 1));
            t0m = fmaxf(t0m, __shfl_xor_sync(0xffffffff, t0m, 2));
            t1m = fmaxf(t1m, __shfl_xor_sync(0xffffffff, t1m, 1));
            t1m = fmaxf(t1m, __shfl_xor_sync(0xffffffff, t1m, 2));

            float mn0 = fmaxf(mv[mi][0], t0m), mn1 = fmaxf(mv[mi][1], t1m);
            cor[mi][0] = __expf(mv[mi][0] - mn0);
            cor[mi][1] = __expf(mv[mi][1] - mn1);
            need_rescale |= (mn0 > mv[mi][0]) || (mn1 > mv[mi][1]);
            mv[mi][0] = mn0; mv[mi][1] = mn1;

            float ps0 = 0.f, ps1 = 0.f;
#pragma unroll
            for (int nt = 0; nt < 4; nt++) {
                float p0 = __expf(sc[mi][nt][0] - mn0);
                float p1 = __expf(sc[mi][nt][1] - mn0);
                float p2 = __expf(sc[mi][nt][2] - mn1);
                float p3 = __expf(sc[mi][nt][3] - mn1);
                ps0 += p0 + p1; ps1 += p2 + p3;
                Ps[w][mi * 16 + r    ][nt * 8 + 2 * c    ] = f2tf(p0);
                Ps[w][mi * 16 + r    ][nt * 8 + 2 * c + 1] = f2tf(p1);
                Ps[w][mi * 16 + r + 8][nt * 8 + 2 * c    ] = f2tf(p2);
                Ps[w][mi * 16 + r + 8][nt * 8 + 2 * c + 1] = f2tf(p3);
            }
            ps0 += __shfl_xor_sync(0xffffffff, ps0, 1);
            ps0 += __shfl_xor_sync(0xffffffff, ps0, 2);
            ps1 += __shfl_xor_sync(0xffffffff, ps1, 1);
            ps1 += __shfl_xor_sync(0xffffffff, ps1, 2);
            lv[mi][0] = lv[mi][0] * cor[mi][0] + ps0;
            lv[mi][1] = lv[mi][1] * cor[mi][1] + ps1;
        }

        if (__ballot_sync(0xffffffff, need_rescale)) {
#pragma unroll
            for (int mi = 0; mi < 2; mi++)
#pragma unroll
                for (int ne = 0; ne < 8; ne++) {
                    o[mi][ne][0] *= cor[mi][0]; o[mi][ne][1] *= cor[mi][0];
                    o[mi][ne][2] *= cor[mi][1]; o[mi][ne][3] *= cor[mi][1];
                }
        }

        __syncwarp();

        // O += P V : P A-frags via LDSM, V B-frags via scalar LDS (reused x2)
#pragma unroll
        for (int k2 = 0; k2 < 4; k2++) {
            uint32_t pa0[4], pa1[4];
            ldsm4(pa0, ps_addr + ((k2 * 8) << 2));
            ldsm4(pa1, ps_addr + ((16 * 36 + k2 * 8) << 2));
#pragma unroll
            for (int ne = 0; ne < 8; ne++) {
                uint32_t bf2[2];
                bf2[0] = Vs[k2 * 8 + c    ][ne * 8 + r];
                bf2[1] = Vs[k2 * 8 + c + 4][ne * 8 + r];
                mma8(o[0][ne], pa0, bf2);
                mma8(o[1][ne], pa1, bf2);
            }
        }
    }

#pragma unroll
    for (int mi = 0; mi < 2; mi++) {
        const float inv0 = 1.f / lv[mi][0], inv1 = 1.f / lv[mi][1];
        const size_t ob = (size_t)(b * SS + s0 + w * 32 + mi * 16) * DD + h * EHD;
#pragma unroll
        for (int ne = 0; ne < 8; ne++) {
            *(float2*)&g_o[ob + (size_t)r       * DD + ne * 8 + 2 * c] =
                make_float2(o[mi][ne][0] * inv0, o[mi][ne][1] * inv0);
            *(float2*)&g_o[ob + (size_t)(r + 8) * DD + ne * 8 + 2 * c] =
                make_float2(o[mi][ne][2] * inv1, o[mi][ne][3] * inv1);
        }
    }
}

// ---------------------------------------------------------------------------
extern "C" void kernel_launch(void* const* d_in, const int* in_sizes, int n_in,
                              void* d_out, int out_size)
{
    (void)in_sizes; (void)n_in; (void)out_size;
    const float* E  = (const float*)d_in[0];
    const float* WQ = (const float*)d_in[1];
    const float* WK = (const float*)d_in[2];
    const float* WV = (const float*)d_in[3];
    const float* WO = (const float*)d_in[4];
    const float* HQ = (const float*)d_in[5];
    const float* HK = (const float*)d_in[6];
    const float* HV = (const float*)d_in[7];
    float* out = (float*)d_out;

    float *wq, *wk, *wv, *q, *k, *v, *o;
    cudaGetSymbolAddress((void**)&wq, g_wq);
    cudaGetSymbolAddress((void**)&wk, g_wk);
    cudaGetSymbolAddress((void**)&wv, g_wv);
    cudaGetSymbolAddress((void**)&q,  g_q);
    cudaGetSymbolAddress((void**)&k,  g_k);
    cudaGetSymbolAddress((void**)&v,  g_v);
    cudaGetSymbolAddress((void**)&o,  g_o);

    dim3 blk(256);

    GemmBatch gw;
    gw.A[0] = HQ; gw.B[0] = WQ; gw.C[0] = wq;
    gw.A[1] = HK; gw.B[1] = WK; gw.C[1] = wk;
    gw.A[2] = HV; gw.B[2] = WV; gw.C[2] = wv;
    gemm_tc<false><<<dim3(DD/128, DD/128, 3), blk>>>(gw, DD, DD, DD);

    GemmBatch ga;
    ga.A[0] = E; ga.B[0] = wq; ga.C[0] = q;
    ga.A[1] = E; ga.B[1] = wk; ga.C[1] = k;
    ga.A[2] = E; ga.B[2] = wv; ga.C[2] = v;
    gemm_tc<true><<<dim3(DD/128, MM/128, 3), blk>>>(ga, MM, DD, DD);

    flash_tc<<<dim3(SS/128, BB*HH), 128>>>();

    GemmBatch go;
    go.A[0] = o; go.B[0] = WO; go.C[0] = out;
    go.A[1] = o; go.B[1] = WO; go.C[1] = out;
    go.A[2] = o; go.B[2] = WO; go.C[2] = out;
    gemm_tc<true><<<dim3(DD/128, MM/128, 1), blk>>>(go, MM, DD, DD);
}

// round 8
// speedup vs baseline: 4.4576x; 1.0989x over previous
#include <cuda_runtime.h>
#include <cstdint>

#define BB 2
#define SS 2048
#define DD 1024
#define HH 16
#define EHD 64
#define MM (BB*SS)   // 4096

__device__ float g_wq[DD*DD];
__device__ float g_wk[DD*DD];
__device__ float g_wv[DD*DD];
__device__ float g_q[MM*DD];
__device__ float g_k[MM*DD];
__device__ float g_v[MM*DD];
__device__ float g_o[MM*DD];

__device__ __forceinline__ uint32_t f2tf(float x) {
    uint32_t u; asm("cvt.rna.tf32.f32 %0, %1;" : "=r"(u) : "f"(x)); return u;
}

template<bool DOCVT>
__device__ __forceinline__ uint4 pack4(float4 v) {
    if (DOCVT)
        return make_uint4(f2tf(v.x), f2tf(v.y), f2tf(v.z), f2tf(v.w));
    return make_uint4(__float_as_uint(v.x), __float_as_uint(v.y),
                      __float_as_uint(v.z), __float_as_uint(v.w));
}

__device__ __forceinline__ uint32_t smem_u32(const void* p) {
    uint32_t a;
    asm("{ .reg .u64 t; cvta.to.shared.u64 t, %1; cvt.u32.u64 %0, t; }"
        : "=r"(a) : "l"(p));
    return a;
}

__device__ __forceinline__ void ldsm4(uint32_t* d, uint32_t addr) {
    asm volatile("ldmatrix.sync.aligned.m8n8.x4.shared.b16 {%0,%1,%2,%3}, [%4];"
        : "=r"(d[0]), "=r"(d[1]), "=r"(d[2]), "=r"(d[3]) : "r"(addr));
}

__device__ __forceinline__ void mma8(float* d, const uint32_t* a, const uint32_t* b) {
    asm volatile("mma.sync.aligned.m16n8k8.row.col.f32.tf32.tf32.f32 "
        "{%0,%1,%2,%3}, {%4,%5,%6,%7}, {%8,%9}, {%0,%1,%2,%3};\n"
        : "+f"(d[0]), "+f"(d[1]), "+f"(d[2]), "+f"(d[3])
        : "r"(a[0]), "r"(a[1]), "r"(a[2]), "r"(a[3]), "r"(b[0]), "r"(b[1]));
}

__device__ __forceinline__ void cp_async16(uint32_t saddr, const void* gaddr) {
    asm volatile("cp.async.ca.shared.global [%0], [%1], 16;"
                 :: "r"(saddr), "l"(gaddr) : "memory");
}

struct GemmBatch {
    const float* A[3];
    const float* B[3];
    float*       C[3];
};

// ---------------------------------------------------------------------------
// TF32 tensor-core GEMM, z-batched, 2-stage smem double-buffer (1 sync/tile),
// LDSM fragments. Static smem = 40 KB.
//  TB=true : C = A[M,K] @ B[N,K]^T ;  TB=false: C = A[M,K] @ B[K,N]
//  CVTA/CVTB: tf32-round on load path (false if operand pre-rounded)
//  CVTC: tf32-round C on store
// ---------------------------------------------------------------------------
template<bool TB, bool CVTA, bool CVTB, bool CVTC>
__global__ __launch_bounds__(256) void gemm_tc(GemmBatch gb, int M, int N, int K)
{
    __shared__ uint32_t As[2][128][20];
    __shared__ uint32_t Bs[2][128][20];
    const float* __restrict__ A  = gb.A[blockIdx.z];
    const float* __restrict__ Bm = gb.B[blockIdx.z];
    float* __restrict__ C        = gb.C[blockIdx.z];

    const int tid  = threadIdx.x;
    const int lane = tid & 31, wid = tid >> 5;
    const int wm = wid & 3, wn = wid >> 2;
    const int m0 = blockIdx.y * 128, n0 = blockIdx.x * 128;
    const int r = lane >> 2, c = lane & 3;

    const int l15   = lane & 15;
    const int khalf = (lane >> 4) & 1;
    const int b_r   = (lane & 7) + ((lane & 16) >> 1);
    const int b_k4  = (lane & 8) >> 1;

    const uint32_t As_base = smem_u32(&As[0][0][0]);
    const uint32_t Bs_base = smem_u32(&Bs[0][0][0]);
    const uint32_t BUFB = 128 * 20 * 4;
    const uint32_t a_addr0 = As_base + (((wm * 32 + l15) * 20 + 4 * khalf) << 2);
    const uint32_t b_addr0 = Bs_base + (((wn * 64 + b_r) * 20 + b_k4) << 2);

    const int arow = tid >> 2, akq = (tid & 3) * 4;      // A / B(TB): rows arow, arow+64
    const int bkk  = tid & 15, bc4 = tid >> 4;           // B(NN)

    float acc[2][8][4] = {};
    float4 pa[2], pb[2];

    auto ldg_tile = [&](int k0) {
        pa[0] = *(const float4*)&A[(size_t)(m0 + arow) * K + k0 + akq];
        pa[1] = *(const float4*)&A[(size_t)(m0 + arow + 64) * K + k0 + akq];
        if (TB) {
            pb[0] = *(const float4*)&Bm[(size_t)(n0 + arow) * K + k0 + akq];
            pb[1] = *(const float4*)&Bm[(size_t)(n0 + arow + 64) * K + k0 + akq];
        } else {
            pb[0] = *(const float4*)&Bm[(size_t)(k0 + bkk) * N + n0 + bc4 * 4];
            pb[1] = *(const float4*)&Bm[(size_t)(k0 + bkk) * N + n0 + (bc4 + 16) * 4];
        }
    };
    auto sts_tile = [&](int buf) {
        *(uint4*)&As[buf][arow][akq]      = pack4<CVTA>(pa[0]);
        *(uint4*)&As[buf][arow + 64][akq] = pack4<CVTA>(pa[1]);
        if (TB) {
            *(uint4*)&Bs[buf][arow][akq]      = pack4<CVTB>(pb[0]);
            *(uint4*)&Bs[buf][arow + 64][akq] = pack4<CVTB>(pb[1]);
        } else {
            uint4 u0 = pack4<CVTB>(pb[0]), u1 = pack4<CVTB>(pb[1]);
            Bs[buf][bc4 * 4 + 0][bkk] = u0.x;
            Bs[buf][bc4 * 4 + 1][bkk] = u0.y;
            Bs[buf][bc4 * 4 + 2][bkk] = u0.z;
            Bs[buf][bc4 * 4 + 3][bkk] = u0.w;
            Bs[buf][(bc4 + 16) * 4 + 0][bkk] = u1.x;
            Bs[buf][(bc4 + 16) * 4 + 1][bkk] = u1.y;
            Bs[buf][(bc4 + 16) * 4 + 2][bkk] = u1.z;
            Bs[buf][(bc4 + 16) * 4 + 3][bkk] = u1.w;
        }
    };

    const int ntiles = K / 16;
    ldg_tile(0);
    sts_tile(0);
    if (ntiles > 1) ldg_tile(16);
    __syncthreads();

    for (int kt = 0; kt < ntiles; kt++) {
        const int buf = kt & 1;
        if (kt + 1 < ntiles) {
            sts_tile(buf ^ 1);
            if (kt + 2 < ntiles) ldg_tile((kt + 2) * 16);
        }

        const uint32_t aoff = buf ? BUFB : 0;
#pragma unroll
        for (int ks = 0; ks < 2; ks++) {
            uint32_t af[2][4], bf[4][4];
            ldsm4(af[0], a_addr0 + aoff + ((ks * 8) << 2));
            ldsm4(af[1], a_addr0 + aoff + ((16 * 20 + ks * 8) << 2));
#pragma unroll
            for (int nj = 0; nj < 4; nj++)
                ldsm4(bf[nj], b_addr0 + aoff + ((nj * 16 * 20 + ks * 8) << 2));
#pragma unroll
            for (int mi = 0; mi < 2; mi++)
#pragma unroll
                for (int ni = 0; ni < 8; ni++)
                    mma8(acc[mi][ni], af[mi], &bf[ni >> 1][(ni & 1) * 2]);
        }
        __syncthreads();
    }

#pragma unroll
    for (int mi = 0; mi < 2; mi++)
#pragma unroll
        for (int ni = 0; ni < 8; ni++) {
            int row = m0 + wm * 32 + mi * 16 + r;
            int col = n0 + wn * 64 + ni * 8 + 2 * c;
            float v0 = acc[mi][ni][0], v1 = acc[mi][ni][1];
            float v2 = acc[mi][ni][2], v3 = acc[mi][ni][3];
            if (CVTC) {
                v0 = __uint_as_float(f2tf(v0)); v1 = __uint_as_float(f2tf(v1));
                v2 = __uint_as_float(f2tf(v2)); v3 = __uint_as_float(f2tf(v3));
            }
            *(float2*)&C[(size_t)row * N + col]       = make_float2(v0, v1);
            *(float2*)&C[(size_t)(row + 8) * N + col] = make_float2(v2, v3);
        }
}

// ---------------------------------------------------------------------------
// Tensor-core flash attention (tf32), 4 warps, 32 q-rows/warp, key tiles 32.
// K/V fed by cp.async, 2 buffers, 2 tile-groups in flight.
// Dynamic smem 54,272 B.  Layout (uint32 offsets):
//   Ks [2][32][68] @ 0,  Vs [2][32][72] @ 4352,  Ps [4][32][36] @ 8960
// ---------------------------------------------------------------------------
#define KS_OFF 0
#define VS_OFF (2*32*68)
#define PS_OFF (VS_OFF + 2*32*72)
#define FLASH_SMEM_BYTES ((PS_OFF + 4*32*36) * 4)

__global__ __launch_bounds__(128, 2) void flash_tc()
{
    extern __shared__ uint32_t dsm[];
    uint32_t* Ks = dsm + KS_OFF;
    uint32_t* Vs = dsm + VS_OFF;
    uint32_t* Ps = dsm + PS_OFF;

    const int tid  = threadIdx.x;
    const int lane = tid & 31, w = tid >> 5;
    const int r = lane >> 2, c = lane & 3;
    const int s0 = blockIdx.x * 128;
    const int bh = blockIdx.y;
    const int h = bh & (HH - 1), b = bh / HH;

    const int l15   = lane & 15;
    const int khalf = (lane >> 4) & 1;
    const int b_r   = (lane & 7) + ((lane & 16) >> 1);
    const int b_k4  = (lane & 8) >> 1;

    const uint32_t KBUF = 32 * 68 * 4;
    const uint32_t ks_base = smem_u32(Ks);
    const uint32_t vs_base = smem_u32(Vs);
    const uint32_t ks_addr = ks_base + ((b_r * 68 + b_k4) << 2);
    const uint32_t ps_addr = smem_u32(Ps + w * 32 * 36) + ((l15 * 36 + 4 * khalf) << 2);

    // Q fragments, pre-scaled by 0.125 (exact on tf32 values; stays tf32)
    uint32_t qa[2][8][4];
#pragma unroll
    for (int mi = 0; mi < 2; mi++) {
        const size_t qb = (size_t)(b * SS + s0 + w * 32 + mi * 16) * DD + h * EHD;
#pragma unroll
        for (int kt = 0; kt < 8; kt++) {
            qa[mi][kt][0] = __float_as_uint(0.125f * g_q[qb + (size_t)r       * DD + kt * 8 + c]);
            qa[mi][kt][1] = __float_as_uint(0.125f * g_q[qb + (size_t)(r + 8) * DD + kt * 8 + c]);
            qa[mi][kt][2] = __float_as_uint(0.125f * g_q[qb + (size_t)r       * DD + kt * 8 + c + 4]);
            qa[mi][kt][3] = __float_as_uint(0.125f * g_q[qb + (size_t)(r + 8) * DD + kt * 8 + c + 4]);
        }
    }

    // cp.async tile loader: 128 threads x 4 rows each = full 32x64 coverage
    const int trow = tid >> 4;            // 0..7
    const int tc4  = (tid & 15) * 4;      // element col
    auto cp_kv = [&](int t0, int buf) {
#pragma unroll
        for (int i = 0; i < 4; i++) {
            const int row = trow + i * 8;                    // 0..31 full coverage
            const size_t g = (size_t)(b * SS + t0 + row) * DD + h * EHD + tc4;
            cp_async16(ks_base + ((buf * 32 * 68 + row * 68 + tc4) << 2), &g_k[g]);
            cp_async16(vs_base + ((buf * 32 * 72 + row * 72 + tc4) << 2), &g_v[g]);
        }
        asm volatile("cp.async.commit_group;" ::: "memory");
    };

    float o[2][8][4] = {};
    float mv[2][2], lv[2][2];
#pragma unroll
    for (int mi = 0; mi < 2; mi++) { mv[mi][0] = mv[mi][1] = -1e30f; lv[mi][0] = lv[mi][1] = 0.f; }

    const int NT = SS / 32;
    cp_kv(0, 0);
    cp_kv(32, 1);

    for (int ti = 0; ti < NT; ti++) {
        const int buf = ti & 1;
        asm volatile("cp.async.wait_group 1;" ::: "memory");   // tile ti landed
        __syncthreads();                                        // visible to all

        const uint32_t koff = buf ? KBUF : 0;

        // S = Q K^T : 32x32 per warp; K B-frags via LDSM
        float sc[2][4][4] = {};
#pragma unroll
        for (int kst = 0; kst < 8; kst++) {
            uint32_t kb[2][4];
            ldsm4(kb[0], ks_addr + koff + ((kst * 8) << 2));
            ldsm4(kb[1], ks_addr + koff + ((16 * 68 + kst * 8) << 2));
#pragma unroll
            for (int nt = 0; nt < 4; nt++) {
                mma8(sc[0][nt], qa[0][kst], &kb[nt >> 1][(nt & 1) * 2]);
                mma8(sc[1][nt], qa[1][kst], &kb[nt >> 1][(nt & 1) * 2]);
            }
        }

        // online softmax per m-tile
        bool need_rescale = false;
        float cor[2][2];
#pragma unroll
        for (int mi = 0; mi < 2; mi++) {
            float t0m = -1e30f, t1m = -1e30f;
#pragma unroll
            for (int nt = 0; nt < 4; nt++) {
                t0m = fmaxf(t0m, fmaxf(sc[mi][nt][0], sc[mi][nt][1]));
                t1m = fmaxf(t1m, fmaxf(sc[mi][nt][2], sc[mi][nt][3]));
            }
            t0m = fmaxf(t0m, __shfl_xor_sync(0xffffffff, t0m, 1));
            t0m = fmaxf(t0m, __shfl_xor_sync(0xffffffff, t0m, 2));
            t1m = fmaxf(t1m, __shfl_xor_sync(0xffffffff, t1m, 1));
            t1m = fmaxf(t1m, __shfl_xor_sync(0xffffffff, t1m, 2));

            float mn0 = fmaxf(mv[mi][0], t0m), mn1 = fmaxf(mv[mi][1], t1m);
            cor[mi][0] = __expf(mv[mi][0] - mn0);
            cor[mi][1] = __expf(mv[mi][1] - mn1);
            need_rescale |= (mn0 > mv[mi][0]) || (mn1 > mv[mi][1]);
            mv[mi][0] = mn0; mv[mi][1] = mn1;

            uint32_t* Pw = Ps + w * 32 * 36;
            float ps0 = 0.f, ps1 = 0.f;
#pragma unroll
            for (int nt = 0; nt < 4; nt++) {
                float p0 = __expf(sc[mi][nt][0] - mn0);
                float p1 = __expf(sc[mi][nt][1] - mn0);
                float p2 = __expf(sc[mi][nt][2] - mn1);
                float p3 = __expf(sc[mi][nt][3] - mn1);
                ps0 += p0 + p1; ps1 += p2 + p3;
                Pw[(mi * 16 + r    ) * 36 + nt * 8 + 2 * c    ] = f2tf(p0);
                Pw[(mi * 16 + r    ) * 36 + nt * 8 + 2 * c + 1] = f2tf(p1);
                Pw[(mi * 16 + r + 8) * 36 + nt * 8 + 2 * c    ] = f2tf(p2);
                Pw[(mi * 16 + r + 8) * 36 + nt * 8 + 2 * c + 1] = f2tf(p3);
            }
            ps0 += __shfl_xor_sync(0xffffffff, ps0, 1);
            ps0 += __shfl_xor_sync(0xffffffff, ps0, 2);
            ps1 += __shfl_xor_sync(0xffffffff, ps1, 1);
            ps1 += __shfl_xor_sync(0xffffffff, ps1, 2);
            lv[mi][0] = lv[mi][0] * cor[mi][0] + ps0;
            lv[mi][1] = lv[mi][1] * cor[mi][1] + ps1;
        }

        if (__ballot_sync(0xffffffff, need_rescale)) {
#pragma unroll
            for (int mi = 0; mi < 2; mi++)
#pragma unroll
                for (int ne = 0; ne < 8; ne++) {
                    o[mi][ne][0] *= cor[mi][0]; o[mi][ne][1] *= cor[mi][0];
                    o[mi][ne][2] *= cor[mi][1]; o[mi][ne][3] *= cor[mi][1];
                }
        }

        __syncwarp();

        // O += P V : P A-frags via LDSM, V B-frags via scalar LDS (broadcast)
        const uint32_t* Vb = Vs + (size_t)buf * 32 * 72;
#pragma unroll
        for (int k2 = 0; k2 < 4; k2++) {
            uint32_t pa0[4], pa1[4];
            ldsm4(pa0, ps_addr + ((k2 * 8) << 2));
            ldsm4(pa1, ps_addr + ((16 * 36 + k2 * 8) << 2));
#pragma unroll
            for (int ne = 0; ne < 8; ne++) {
                uint32_t bf2[2];
                bf2[0] = Vb[(k2 * 8 + c    ) * 72 + ne * 8 + r];
                bf2[1] = Vb[(k2 * 8 + c + 4) * 72 + ne * 8 + r];
                mma8(o[0][ne], pa0, bf2);
                mma8(o[1][ne], pa1, bf2);
            }
        }

        __syncthreads();                       // all warps done reading buf
        if (ti + 2 < NT) cp_kv((ti + 2) * 32, buf);   // refill just-freed buffer
    }

#pragma unroll
    for (int mi = 0; mi < 2; mi++) {
        const float inv0 = 1.f / lv[mi][0], inv1 = 1.f / lv[mi][1];
        const size_t ob = (size_t)(b * SS + s0 + w * 32 + mi * 16) * DD + h * EHD;
#pragma unroll
        for (int ne = 0; ne < 8; ne++) {
            *(float2*)&g_o[ob + (size_t)r * DD + ne * 8 + 2 * c] =
                make_float2(__uint_as_float(f2tf(o[mi][ne][0] * inv0)),
                            __uint_as_float(f2tf(o[mi][ne][1] * inv0)));
            *(float2*)&g_o[ob + (size_t)(r + 8) * DD + ne * 8 + 2 * c] =
                make_float2(__uint_as_float(f2tf(o[mi][ne][2] * inv1)),
                            __uint_as_float(f2tf(o[mi][ne][3] * inv1)));
        }
    }
}

// ---------------------------------------------------------------------------
extern "C" void kernel_launch(void* const* d_in, const int* in_sizes, int n_in,
                              void* d_out, int out_size)
{
    (void)in_sizes; (void)n_in; (void)out_size;
    const float* E  = (const float*)d_in[0];
    const float* WQ = (const float*)d_in[1];
    const float* WK = (const float*)d_in[2];
    const float* WV = (const float*)d_in[3];
    const float* WO = (const float*)d_in[4];
    const float* HQ = (const float*)d_in[5];
    const float* HK = (const float*)d_in[6];
    const float* HV = (const float*)d_in[7];
    float* out = (float*)d_out;

    float *wq, *wk, *wv, *q, *k, *v, *o;
    cudaGetSymbolAddress((void**)&wq, g_wq);
    cudaGetSymbolAddress((void**)&wk, g_wk);
    cudaGetSymbolAddress((void**)&wv, g_wv);
    cudaGetSymbolAddress((void**)&q,  g_q);
    cudaGetSymbolAddress((void**)&k,  g_k);
    cudaGetSymbolAddress((void**)&v,  g_v);
    cudaGetSymbolAddress((void**)&o,  g_o);

    cudaFuncSetAttribute(flash_tc, cudaFuncAttributeMaxDynamicSharedMemorySize,
                         FLASH_SMEM_BYTES);

    dim3 blk(256);

    // 1) Weff = HXcat @ WX (NN). A,B external -> cvt; C pre-rounded.
    GemmBatch gw;
    gw.A[0] = HQ; gw.B[0] = WQ; gw.C[0] = wq;
    gw.A[1] = HK; gw.B[1] = WK; gw.C[1] = wk;
    gw.A[2] = HV; gw.B[2] = WV; gw.C[2] = wv;
    gemm_tc<false, true, true, true><<<dim3(DD/128, DD/128, 3), blk>>>(gw, DD, DD, DD);

    // 2) q/k/v = E @ Weff^T (NT). A external -> cvt; B pre-rounded; C pre-rounded.
    GemmBatch ga;
    ga.A[0] = E; ga.B[0] = wq; ga.C[0] = q;
    ga.A[1] = E; ga.B[1] = wk; ga.C[1] = k;
    ga.A[2] = E; ga.B[2] = wv; ga.C[2] = v;
    gemm_tc<true, true, false, true><<<dim3(DD/128, MM/128, 3), blk>>>(ga, MM, DD, DD);

    // 3) attention (writes tf32-rounded o)
    flash_tc<<<dim3(SS/128, BB*HH), 128, FLASH_SMEM_BYTES>>>();

    // 4) out = o @ WO^T. A pre-rounded; B external -> cvt; C full fp32.
    GemmBatch go;
    go.A[0] = o; go.B[0] = WO; go.C[0] = out;
    go.A[1] = o; go.B[1] = WO; go.C[1] = out;
    go.A[2] = o; go.B[2] = WO; go.C[2] = out;
    gemm_tc<true, false, true, false><<<dim3(DD/128, MM/128, 1), blk>>>(go, MM, DD, DD);
}